// round 16
// baseline (speedup 1.0000x reference)
#include <cuda_runtime.h>
#include <cstdint>
#include <math.h>

#define BB 512
#define MM 4096
#define DD 64
#define CC 256
#define NT 288                    // 9 warps: 8 consumers + 1 producer
#define NW 9
#define NTE 256                   // threads doing epilogue element work
#define TILE 32                   // rows per tile
#define TILE_BYTES 8192           // 32 rows * 256 B contiguous
#define TILE4 512                 // float4 per tile
#define NTILES 128                // tiles per batch
#define NBUF 4                    // ring slots
#define RPT (MM / NTE)            // 16
#define EPSF 1e-8f
#define LOG2E 1.442695040888963f

// smem floats: 16 (4 full + 4 empty mbarriers, 64B) + buf + SA + misc
#define SMEM_FLOATS (16 + NBUF * TILE4 * 4 + MM + CC + DD + 16 + 6 + 6)
#define SMEM_BYTES (SMEM_FLOATS * 4)

// ---- software exp2 / log2 (FMA-pipe transcendentals) ----
__device__ __forceinline__ float fast_exp2(float y) {
    y = fmaxf(y, -250.0f);
    float t = y + 12582912.0f;
    int   ni = __float_as_int(t) - 0x4B400000;
    float f = y - (t - 12582912.0f);
    float p = 1.52527338e-5f;
    p = fmaf(p, f, 1.54035304e-4f);
    p = fmaf(p, f, 1.33335581e-3f);
    p = fmaf(p, f, 9.61812911e-3f);
    p = fmaf(p, f, 5.55041087e-2f);
    p = fmaf(p, f, 2.40226507e-1f);
    p = fmaf(p, f, 6.93147181e-1f);
    p = fmaf(p, f, 1.0f);
    int n1 = ni >> 1;
    int n2 = ni - n1;
    float s1 = __int_as_float((n1 + 127) << 23);
    float s2 = __int_as_float((n2 + 127) << 23);
    return p * s1 * s2;
}

__device__ __forceinline__ float fast_log2(float x) {
    int ix = __float_as_int(x);
    int e = ((ix >> 23) & 0xff) - 127;
    float m = __int_as_float((ix & 0x007fffff) | 0x3f800000);
    if (m > 1.41421356f) { m *= 0.5f; e += 1; }
    float s = __fdividef(m - 1.0f, m + 1.0f);
    float s2 = s * s;
    float p = 0.111111111f;
    p = fmaf(p, s2, 0.142857143f);
    p = fmaf(p, s2, 0.2f);
    p = fmaf(p, s2, 0.333333333f);
    p = fmaf(p, s2, 1.0f);
    float lnm = 2.0f * s * p;
    return (float)e + lnm * LOG2E;
}

__device__ __forceinline__ float fast_exp(float z) { return fast_exp2(z * LOG2E); }
__device__ __forceinline__ float fast_pow(float x, float g) { return fast_exp2(g * fast_log2(x)); }

// block reductions over 9 warps (all 288 threads must call)
__device__ __forceinline__ float blockReduceSum(float v, float* sh) {
    int lane = threadIdx.x & 31, wid = threadIdx.x >> 5;
    #pragma unroll
    for (int o = 16; o; o >>= 1) v += __shfl_xor_sync(0xffffffffu, v, o);
    __syncthreads();
    if (lane == 0) sh[wid] = v;
    __syncthreads();
    if (wid == 0) {
        float x = (lane < NW) ? sh[lane] : 0.0f;
        #pragma unroll
        for (int o = 8; o; o >>= 1) x += __shfl_xor_sync(0xffffffffu, x, o);
        if (lane == 0) sh[0] = x;
    }
    __syncthreads();
    return sh[0];
}

__device__ __forceinline__ float blockReduceMax(float v, float* sh) {
    int lane = threadIdx.x & 31, wid = threadIdx.x >> 5;
    #pragma unroll
    for (int o = 16; o; o >>= 1) v = fmaxf(v, __shfl_xor_sync(0xffffffffu, v, o));
    __syncthreads();
    if (lane == 0) sh[wid] = v;
    __syncthreads();
    if (wid == 0) {
        float x = (lane < NW) ? sh[lane] : -INFINITY;
        #pragma unroll
        for (int o = 8; o; o >>= 1) x = fmaxf(x, __shfl_xor_sync(0xffffffffu, x, o));
        if (lane == 0) sh[0] = x;
    }
    __syncthreads();
    return sh[0];
}

// acquire-parity wait on an smem mbarrier (HW sleep)
__device__ __forceinline__ void mbar_wait(uint32_t mbar, uint32_t parity) {
    asm volatile(
        "{\n\t"
        ".reg .pred P;\n\t"
        "WAIT_%=:\n\t"
        "mbarrier.try_wait.parity.acquire.cta.shared::cta.b64 P, [%0], %1, 0x989680;\n\t"
        "@!P bra WAIT_%=;\n\t"
        "}"
        :: "r"(mbar), "r"(parity) : "memory");
}

__device__ __forceinline__ void mbar_arrive(uint32_t mbar) {
    asm volatile("mbarrier.arrive.release.cta.shared::cta.b64 _, [%0];"
                 :: "r"(mbar) : "memory");
}

// arm full[slot] and launch one 8 KB TMA bulk copy
__device__ __forceinline__ void issue_tile(const float* batch_base, int g,
                                           uint32_t buf_u32, uint32_t full_u32) {
    int slot = g & (NBUF - 1);
    const float* src = batch_base + (size_t)g * TILE * DD;
    uint32_t dst = buf_u32 + (uint32_t)slot * TILE_BYTES;
    uint32_t mb  = full_u32 + (uint32_t)(slot * 8);
    asm volatile("mbarrier.arrive.expect_tx.shared::cta.b64 _, [%0], %1;"
                 :: "r"(mb), "r"(TILE_BYTES) : "memory");
    asm volatile("cp.async.bulk.shared::cta.global.mbarrier::complete_tx::bytes "
                 "[%0], [%1], %2, [%3];"
                 :: "r"(dst), "l"(src), "r"(TILE_BYTES), "r"(mb) : "memory");
}

__global__ __launch_bounds__(NT, 4)
void ntm_head_kernel(
    const float* __restrict__ memory,     // (B, M, D)
    const float* __restrict__ cstate,     // (B, C)
    const float* __restrict__ prevw,      // (B, M)
    const float* __restrict__ Wk,         // (C, D)
    const float* __restrict__ Wb,
    const float* __restrict__ bb,
    const float* __restrict__ Wgate,
    const float* __restrict__ bgate,
    const float* __restrict__ Ws,
    const float* __restrict__ bs,
    const float* __restrict__ Wg,
    const float* __restrict__ bg,
    float* __restrict__ out)              // (B, M)
{
    extern __shared__ float smem[];
    // [0..8): full mbarriers (4 x 8B = 32B), [8..16): empty mbarriers (32B)
    float4* buf     = reinterpret_cast<float4*>(smem + 16);  // NBUF * TILE4
    float*  SA      = smem + 16 + NBUF * TILE4 * 4;           // MM
    float*  sh_cs   = SA + MM;                                // CC
    float*  sh_qn   = sh_cs + CC;                             // DD
    float*  sh_red  = sh_qn + DD;                             // 16
    float*  sh_scal = sh_red + 16;                            // 6
    float*  sh_par  = sh_scal + 6;                            // 6

    const int tid  = threadIdx.x;
    const int lane = tid & 31;
    const int wid  = tid >> 5;
    const int b    = blockIdx.x;

    const uint32_t full_u32  = (uint32_t)__cvta_generic_to_shared(smem);
    const uint32_t empty_u32 = full_u32 + 32;
    const uint32_t buf_u32   = (uint32_t)__cvta_generic_to_shared(buf);
    const float* batch_base  = memory + (size_t)b * MM * DD;

    // ---- init mbarriers: full count=1 (TMA tx), empty count=8 (consumer warps)
    if (tid == 0) {
        #pragma unroll
        for (int s = 0; s < NBUF; s++) {
            asm volatile("mbarrier.init.shared::cta.b64 [%0], 1;"
                         :: "r"(full_u32 + (uint32_t)(s * 8)) : "memory");
            asm volatile("mbarrier.init.shared::cta.b64 [%0], 8;"
                         :: "r"(empty_u32 + (uint32_t)(s * 8)) : "memory");
        }
    }
    __syncthreads();
    if (tid == 0) {
        asm volatile("fence.proxy.async.shared::cta;" ::: "memory");
        #pragma unroll
        for (int g = 0; g < NBUF; g++)
            issue_tile(batch_base, g, buf_u32, full_u32);
    }

    // ================= preamble (under in-flight DMA) =================
    if (tid < CC) sh_cs[tid] = cstate[(size_t)b * CC + tid];
    __syncthreads();

    if (tid < DD) {
        float acc = 0.0f;
        #pragma unroll 8
        for (int c = 0; c < CC; c++) acc = fmaf(sh_cs[c], Wk[c * DD + tid], acc);
        sh_qn[tid] = acc;
    }
    if (wid >= 2 && wid < 8) {
        int s = wid - 2;
        float acc = 0.0f;
        if (s < 3) {
            const float* W = (s == 0) ? Wb : (s == 1) ? Wgate : Wg;
            for (int c = lane; c < CC; c += 32) acc = fmaf(sh_cs[c], W[c], acc);
        } else {
            int col = s - 3;
            for (int c = lane; c < CC; c += 32) acc = fmaf(sh_cs[c], Ws[c * 3 + col], acc);
        }
        #pragma unroll
        for (int o = 16; o; o >>= 1) acc += __shfl_xor_sync(0xffffffffu, acc, o);
        if (lane == 0) sh_scal[s] = acc;
    }
    __syncthreads();

    if (wid == 0) {
        float a = sh_qn[lane], c = sh_qn[lane + 32];
        float v = a * a + c * c;
        #pragma unroll
        for (int o = 16; o; o >>= 1) v += __shfl_xor_sync(0xffffffffu, v, o);
        float inv = 1.0f / (sqrtf(v) + EPSF);
        sh_qn[lane]      = a * inv;
        sh_qn[lane + 32] = c * inv;
    }
    if (tid == 32) {
        sh_par[0] = log1pf(__expf(sh_scal[0] + bb[0])) + 1.0f;            // beta
        sh_par[1] = 1.0f / (1.0f + __expf(-(sh_scal[1] + bgate[0])));     // gate
        sh_par[2] = log1pf(__expf(sh_scal[2] + bg[0])) + 1.0f;            // gamma
        float a0 = sh_scal[3] + bs[0];
        float a1 = sh_scal[4] + bs[1];
        float a2 = sh_scal[5] + bs[2];
        float mx = fmaxf(a0, fmaxf(a1, a2));
        float e0 = __expf(a0 - mx), e1 = __expf(a1 - mx), e2 = __expf(a2 - mx);
        float inv = 1.0f / (e0 + e1 + e2);
        sh_par[3] = e0 * inv; sh_par[4] = e1 * inv; sh_par[5] = e2 * inv;
    }
    __syncthreads();

    // ================= warp-specialized stream =================
    if (wid == 8) {
        // ---- producer: sole waiter on each empty barrier, phases in order
        if (lane == 0) {
            for (int g = NBUF; g < NTILES; g++) {
                int s = g & (NBUF - 1);
                int k = g >> 2;                    // phase of full[s] for tile g
                mbar_wait(empty_u32 + (uint32_t)(s * 8), (uint32_t)((k - 1) & 1));
                issue_tile(batch_base, g, buf_u32, full_u32);
            }
        }
    } else {
        // ---- consumers: every warp consumes EVERY tile (4 rows each),
        //      so each waiter sees every phase of full[s] in order.
        const int li  = lane & 7;
        const int row = wid * 4 + (lane >> 3);     // this warp's rows in each tile
        float4 q0, q1;
        {
            const float4* qn4 = reinterpret_cast<const float4*>(sh_qn);
            q0 = qn4[li];
            q1 = qn4[li + 8];
        }

        for (int g = 0; g < NTILES; g++) {
            const int s = g & (NBUF - 1);
            mbar_wait(full_u32 + (uint32_t)(s * 8), (uint32_t)((g >> 2) & 1));

            const float4* rp = buf + (size_t)s * TILE4 + row * 16 + li;
            float4 v0 = rp[0];
            float4 v1 = rp[8];
            float dot = v0.x * q0.x, ss = v0.x * v0.x;
            dot = fmaf(v0.y, q0.y, dot); ss = fmaf(v0.y, v0.y, ss);
            dot = fmaf(v0.z, q0.z, dot); ss = fmaf(v0.z, v0.z, ss);
            dot = fmaf(v0.w, q0.w, dot); ss = fmaf(v0.w, v0.w, ss);
            dot = fmaf(v1.x, q1.x, dot); ss = fmaf(v1.x, v1.x, ss);
            dot = fmaf(v1.y, q1.y, dot); ss = fmaf(v1.y, v1.y, ss);
            dot = fmaf(v1.z, q1.z, dot); ss = fmaf(v1.z, v1.z, ss);
            dot = fmaf(v1.w, q1.w, dot); ss = fmaf(v1.w, v1.w, ss);
            #pragma unroll
            for (int o = 1; o < 8; o <<= 1) {
                dot += __shfl_xor_sync(0xffffffffu, dot, o);
                ss  += __shfl_xor_sync(0xffffffffu, ss,  o);
            }
            if (li == 0)
                SA[g * TILE + row] = dot * rsqrtf(ss);

            __syncwarp();                        // all lanes' reads done
            if (lane == 0)
                mbar_arrive(empty_u32 + (uint32_t)(s * 8));
        }
    }
    __syncthreads();   // all sims in SA; producer rejoins

    // ================= epilogue (all 288 join reductions) =================
    const float beta = sh_par[0];
    float lmax = -INFINITY;
    if (tid < NTE) {
        #pragma unroll
        for (int k = 0; k < RPT; k++) lmax = fmaxf(lmax, SA[tid + k * NTE]);
    }
    const float smax = blockReduceMax(lmax, sh_red) * beta;

    float lsum = 0.0f;
    if (tid < NTE) {
        #pragma unroll
        for (int k = 0; k < RPT; k++) {
            int m = tid + k * NTE;
            float e = fast_exp(fmaf(beta, SA[m], -smax));
            SA[m] = e;
            lsum += e;
        }
    }
    const float invsum = 1.0f / blockReduceSum(lsum, sh_red);

    const float gate = sh_par[1], gate1 = 1.0f - sh_par[1];
    const float* pw = prevw + (size_t)b * MM;
    if (tid < NTE) {
        #pragma unroll
        for (int k = 0; k < RPT; k++) {
            int m = tid + k * NTE;
            SA[m] = fmaf(gate, SA[m] * invsum, gate1 * pw[m]);
        }
    }
    __syncthreads();

    const float gamma = sh_par[2];
    const float s0 = sh_par[3], s1 = sh_par[4], s2 = sh_par[5];
    float p[RPT];
    float psum = 0.0f;
    if (tid < NTE) {
        #pragma unroll
        for (int k = 0; k < RPT; k++) {
            int m  = tid + k * NTE;
            int ml = (m == 0)      ? MM - 1 : m - 1;
            int mr = (m == MM - 1) ? 0      : m + 1;
            float sv = SA[ml] * s0 + SA[m] * s1 + SA[mr] * s2;
            p[k] = fast_pow(sv + EPSF, gamma);
            psum += p[k];
        }
    }
    psum = blockReduceSum(psum, sh_red);
    const float invp = 1.0f / (psum + EPSF);

    if (tid < NTE) {
        float* ob = out + (size_t)b * MM;
        #pragma unroll
        for (int k = 0; k < RPT; k++) {
            int m = tid + k * NTE;
            ob[m] = p[k] * invp;
        }
    }
}

extern "C" void kernel_launch(void* const* d_in, const int* in_sizes, int n_in,
                              void* d_out, int out_size) {
    const float* memory = (const float*)d_in[0];
    const float* cstate = (const float*)d_in[1];
    const float* prevw  = (const float*)d_in[2];
    const float* Wk     = (const float*)d_in[3];
    const float* Wb     = (const float*)d_in[4];
    const float* bb     = (const float*)d_in[5];
    const float* Wgate  = (const float*)d_in[6];
    const float* bgate  = (const float*)d_in[7];
    const float* Ws     = (const float*)d_in[8];
    const float* bs     = (const float*)d_in[9];
    const float* Wg     = (const float*)d_in[10];
    const float* bg     = (const float*)d_in[11];
    float* out = (float*)d_out;

    static int smem_set = 0;
    if (!smem_set) {
        cudaFuncSetAttribute(ntm_head_kernel,
                             cudaFuncAttributeMaxDynamicSharedMemorySize,
                             SMEM_BYTES);
        smem_set = 1;
    }

    ntm_head_kernel<<<BB, NT, SMEM_BYTES>>>(memory, cstate, prevw,
                                            Wk, Wb, bb, Wgate, bgate,
                                            Ws, bs, Wg, bg, out);
}